// round 10
// baseline (speedup 1.0000x reference)
#include <cuda_runtime.h>
#include <cuda_fp16.h>
#include <math.h>
#include <stdint.h>

// Problem constants
#define T_TOK 4096
#define D_DIM 1024
#define E_NUM 8
#define F_DIM 2048
#define F2    4096
#define CAP   4096

// Tile config: CTA 128x256, warp tile 64x64 (2x4 warp grid), BK=64 fp16
#define BM 128
#define BN 256
#define BK 64
#define MAT_A 16384                   // A tile: 128 rows x 128B
#define MAT_B 32768                   // B tile: 256 rows x 128B
#define STAGE (MAT_A + MAT_B)         // 49152
#define NSTAGE 4
#define SMEM_BYTES (NSTAGE * STAGE)   // 196608

// ---------------- scratch (device globals; no allocs allowed) ----------------
__device__ int   g_cnt[E_NUM];
__device__ int   g_tok[E_NUM * CAP];
__device__ int   g_t2e[T_TOK * 2];
__device__ float g_t2w[T_TOK * 2];
__device__ __half g_H[(size_t)E_NUM * CAP * F_DIM];
__device__ float  g_y[(size_t)E_NUM * CAP * D_DIM];
__device__ __half g_x16[(size_t)T_TOK * D_DIM];
__device__ __half g_w116[(size_t)E_NUM * F2 * D_DIM];
__device__ __half g_w216[(size_t)E_NUM * D_DIM * F_DIM];

// ---------------- helpers ----------------
__device__ __forceinline__ uint32_t smem_u32(const void* p) {
    uint32_t a;
    asm("{ .reg .u64 t; cvta.to.shared.u64 t, %1; cvt.u32.u64 %0, t; }" : "=r"(a) : "l"(p));
    return a;
}
__device__ __forceinline__ void ldsm_x4(uint32_t& r0, uint32_t& r1, uint32_t& r2, uint32_t& r3,
                                        uint32_t addr) {
    asm volatile("ldmatrix.sync.aligned.m8n8.x4.shared.b16 {%0,%1,%2,%3}, [%4];"
                 : "=r"(r0), "=r"(r1), "=r"(r2), "=r"(r3) : "r"(addr));
}
__device__ __forceinline__ void mma_f16(float* c,
                                        uint32_t a0, uint32_t a1, uint32_t a2, uint32_t a3,
                                        uint32_t b0, uint32_t b1) {
    asm volatile("mma.sync.aligned.m16n8k16.row.col.f32.f16.f16.f32 "
                 "{%0,%1,%2,%3}, {%4,%5,%6,%7}, {%8,%9}, {%0,%1,%2,%3};"
                 : "+f"(c[0]), "+f"(c[1]), "+f"(c[2]), "+f"(c[3])
                 : "r"(a0), "r"(a1), "r"(a2), "r"(a3), "r"(b0), "r"(b1));
}
#define CP16(dst, src) \
    asm volatile("cp.async.cg.shared.global [%0], [%1], 16;" :: "r"(dst), "l"(src) : "memory")
#define CP_COMMIT() asm volatile("cp.async.commit_group;" ::: "memory")
#define CP_WAIT2()  asm volatile("cp.async.wait_group 2;" ::: "memory")
#define CP_WAIT0()  asm volatile("cp.async.wait_group 0;" ::: "memory")

// swizzled byte offset within a Nx128B matrix: 16B chunk ch in [0,8)
#define SWOFF(row, ch) ((row) * 128 + (((ch) * 16) ^ (((row) & 7) << 4)))

// ---------------- kernel: fp32 -> fp16 convert ----------------
__global__ void cvt_kernel(const float* __restrict__ src,
                           __half* __restrict__ dst, int n4) {
    int i = blockIdx.x * blockDim.x + threadIdx.x;
    int stride = gridDim.x * blockDim.x;
    for (; i < n4; i += stride) {
        float4 v = ((const float4*)src)[i];
        __half2 p0 = __floats2half2_rn(v.x, v.y);
        __half2 p1 = __floats2half2_rn(v.z, v.w);
        *(uint2*)(dst + 4 * (size_t)i) =
            make_uint2(*(uint32_t*)&p0, *(uint32_t*)&p1);
    }
}

// ---------------- kernel 0: reset counters ----------------
__global__ void zero_cnt_kernel() {
    if (threadIdx.x < E_NUM) g_cnt[threadIdx.x] = 0;
}

// ---------------- kernel 1: gating + top-2 routing (fp32, exact) ----------------
__global__ void gate_kernel(const float* __restrict__ x,
                            const float* __restrict__ gw) {
    int t = blockIdx.x;
    __shared__ float xs[D_DIM];
    __shared__ float gates[E_NUM];
    int tid = threadIdx.x;
    for (int i = tid; i < D_DIM; i += blockDim.x)
        xs[i] = x[(size_t)t * D_DIM + i];
    __syncthreads();
    int wid = tid >> 5, lane = tid & 31;
    float s = 0.f;
    for (int d = lane; d < D_DIM; d += 32)
        s += xs[d] * gw[d * E_NUM + wid];
    #pragma unroll
    for (int o = 16; o > 0; o >>= 1)
        s += __shfl_down_sync(0xffffffffu, s, o);
    if (lane == 0) gates[wid] = s;
    __syncthreads();
    if (tid == 0) {
        int i0 = 0; float g0 = gates[0];
        #pragma unroll
        for (int e = 1; e < E_NUM; e++)
            if (gates[e] > g0) { g0 = gates[e]; i0 = e; }
        int i1 = -1; float g1 = -1e30f;
        #pragma unroll
        for (int e = 0; e < E_NUM; e++)
            if (e != i0 && gates[e] > g1) { g1 = gates[e]; i1 = e; }
        float ex = expf(g1 - g0);
        float w0 = 1.f / (1.f + ex);
        float w1 = ex / (1.f + ex);
        int s0 = atomicAdd(&g_cnt[i0], 1);
        int s1 = atomicAdd(&g_cnt[i1], 1);
        g_tok[i0 * CAP + s0] = t;
        g_tok[i1 * CAP + s1] = t;
        g_t2e[t * 2 + 0] = i0 * CAP + s0;
        g_t2e[t * 2 + 1] = i1 * CAP + s1;
        g_t2w[t * 2 + 0] = w0;
        g_t2w[t * 2 + 1] = w1;
    }
}

// ======================================================================
// GEMMs: CTA 128x256x64, 8 warps (2 m x 4 n), warp tile 64x64,
// m16n8k16 fp16, 4-stage cp.async ring, ONE sync per chunk.
// ======================================================================

#define LDSM_OFFSETS() \
    const int lj = lane >> 3, lr = lane & 7; \
    int a_row[4], a_sw[4], b_row[4], b_sw[4]; \
    const int a_chb = (lj >> 1) * 16; \
    const int b_chb = (lj & 1) * 16; \
    _Pragma("unroll") \
    for (int mt = 0; mt < 4; mt++) { \
        int ra = warp_m * 64 + mt * 16 + (lj & 1) * 8 + lr; \
        a_row[mt] = ra * 128; a_sw[mt] = (ra & 7) << 4; \
    } \
    _Pragma("unroll") \
    for (int np = 0; np < 4; np++) { \
        int rb = warp_n * 64 + np * 16 + (lj >> 1) * 8 + lr; \
        b_row[np] = rb * 128; b_sw[np] = (rb & 7) << 4; \
    }

#define MMA_COMPUTE(base) do { \
    _Pragma("unroll") \
    for (int kk = 0; kk < 4; kk++) { \
        uint32_t af[4][4]; \
        _Pragma("unroll") \
        for (int mt = 0; mt < 4; mt++) \
            ldsm_x4(af[mt][0], af[mt][1], af[mt][2], af[mt][3], \
                    (base) + a_row[mt] + ((kk * 32 + a_chb) ^ a_sw[mt])); \
        _Pragma("unroll") \
        for (int np = 0; np < 4; np++) { \
            uint32_t bf[4]; \
            ldsm_x4(bf[0], bf[1], bf[2], bf[3], \
                    (base) + MAT_A + b_row[np] + ((kk * 32 + b_chb) ^ b_sw[np])); \
            _Pragma("unroll") \
            for (int mt = 0; mt < 4; mt++) { \
                mma_f16(acc[mt][2 * np],     af[mt][0], af[mt][1], af[mt][2], af[mt][3], bf[0], bf[1]); \
                mma_f16(acc[mt][2 * np + 1], af[mt][0], af[mt][1], af[mt][2], af[mt][3], bf[2], bf[3]); \
            } \
        } \
    } } while (0)

// ---------------- kernel 2: GEMM1 (h = x @ W1^T + b1) + SwiGLU -> fp16 H ----------------
__global__ void __launch_bounds__(256) ffn1_mma(const float* __restrict__ b1) {
    extern __shared__ char smem[];
    __shared__ int stok[128];
    const int e = blockIdx.z;
    const int cnt = g_cnt[e];
    const int row0 = blockIdx.y * BM;
    if (row0 >= cnt) return;
    const int c0 = blockIdx.x * BN;

    const int tid = threadIdx.x;
    const int lane = tid & 31;
    const int warp_m = (tid >> 5) & 1;   // 2 m-groups of 64
    const int warp_n = tid >> 6;         // 4 n-groups of 64
    const uint32_t sb = smem_u32(smem);

    if (tid < 128) {
        int r = row0 + tid;
        stok[tid] = (r < cnt) ? g_tok[e * CAP + r] : g_tok[e * CAP];
    }
    __syncthreads();

    LDSM_OFFSETS();

    float acc[4][8][4];
    #pragma unroll
    for (int i = 0; i < 4; i++)
        #pragma unroll
        for (int j = 0; j < 8; j++)
            #pragma unroll
            for (int k = 0; k < 4; k++) acc[i][j][k] = 0.f;

    const int NCHUNK = D_DIM / BK;   // 16

    // A: 1024 16B-chunks (4/thread); B: 2048 chunks (8/thread)
    #define G1_ISSUE(c, buf) do { \
        int k0 = (c) * BK; \
        uint32_t st = sb + (buf) * STAGE; \
        _Pragma("unroll") \
        for (int j = 0; j < 4; j++) { \
            int idx = tid + 256 * j; \
            int row = idx >> 3, ch = idx & 7; \
            CP16(st + SWOFF(row, ch), \
                 g_x16 + (size_t)stok[row] * D_DIM + k0 + ch * 8); \
        } \
        _Pragma("unroll") \
        for (int j = 0; j < 8; j++) { \
            int idx = tid + 256 * j; \
            int row = idx >> 3, ch = idx & 7; \
            CP16(st + MAT_A + SWOFF(row, ch), \
                 g_w116 + ((size_t)e * F2 + c0 + row) * D_DIM + k0 + ch * 8); \
        } } while (0)

    G1_ISSUE(0, 0); CP_COMMIT();
    G1_ISSUE(1, 1); CP_COMMIT();
    G1_ISSUE(2, 2); CP_COMMIT();

    #pragma unroll 1
    for (int c = 0; c < NCHUNK; c++) {
        CP_WAIT2();
        __syncthreads();             // data(c) visible AND all warps done with c-1
        if (c + 3 < NCHUNK) G1_ISSUE(c + 3, (c + 3) & 3);
        CP_COMMIT();
        MMA_COMPUTE(sb + (c & 3) * STAGE);
    }
    #undef G1_ISSUE

    CP_WAIT0();
    __syncthreads();

    // epilogue: bias + SwiGLU -> smem repack -> coalesced fp16 stores
    __half* hs = (__half*)smem;      // 128 rows x 128 halves = 32KB
    #pragma unroll
    for (int mt = 0; mt < 4; mt++) {
        #pragma unroll
        for (int dd = 0; dd < 2; dd++) {
            int lrow = warp_m * 64 + mt * 16 + dd * 8 + (lane >> 2);
            #pragma unroll
            for (int nt = 0; nt < 8; nt++) {
                int colp = c0 + warp_n * 64 + nt * 8 + (lane & 3) * 2;
                float g = acc[mt][nt][dd * 2]     + b1[e * F2 + colp];
                float v = acc[mt][nt][dd * 2 + 1] + b1[e * F2 + colp + 1];
                g = fminf(g, 9.0f);
                v = fmaxf(fminf(v, 9.0f), -9.0f);
                float sig = 1.0f / (1.0f + __expf(-1.702f * g));
                float h = g * sig * (v + 1.0f);
                int hcol = warp_n * 32 + nt * 4 + (lane & 3);
                hs[lrow * 128 + hcol] = __float2half_rn(h);
            }
        }
    }
    __syncthreads();
    #pragma unroll
    for (int j = 0; j < 8; j++) {
        int idx = tid + 256 * j;          // 2048 uint4
        int r = idx >> 4, q = idx & 15;
        if (row0 + r < cnt)
            *(uint4*)(g_H + ((size_t)e * CAP + row0 + r) * F_DIM + (c0 >> 1) + q * 8) =
                ((const uint4*)hs)[idx];
    }
}

// ---------------- kernel 3: GEMM2 (y = H @ W2^T + b2) ----------------
__global__ void __launch_bounds__(256) ffn2_mma(const float* __restrict__ b2) {
    extern __shared__ char smem[];
    const int e = blockIdx.z;
    const int cnt = g_cnt[e];
    const int row0 = blockIdx.y * BM;
    if (row0 >= cnt) return;
    const int d0 = blockIdx.x * BN;

    const int tid = threadIdx.x;
    const int lane = tid & 31;
    const int warp_m = (tid >> 5) & 1;
    const int warp_n = tid >> 6;
    const uint32_t sb = smem_u32(smem);

    LDSM_OFFSETS();

    float acc[4][8][4];
    #pragma unroll
    for (int i = 0; i < 4; i++)
        #pragma unroll
        for (int j = 0; j < 8; j++)
            #pragma unroll
            for (int k = 0; k < 4; k++) acc[i][j][k] = 0.f;

    const int NCHUNK = F_DIM / BK;   // 32

    #define G2_ISSUE(c, buf) do { \
        int k0 = (c) * BK; \
        uint32_t st = sb + (buf) * STAGE; \
        _Pragma("unroll") \
        for (int j = 0; j < 4; j++) { \
            int idx = tid + 256 * j; \
            int row = idx >> 3, ch = idx & 7; \
            CP16(st + SWOFF(row, ch), \
                 g_H + ((size_t)e * CAP + row0 + row) * F_DIM + k0 + ch * 8); \
        } \
        _Pragma("unroll") \
        for (int j = 0; j < 8; j++) { \
            int idx = tid + 256 * j; \
            int row = idx >> 3, ch = idx & 7; \
            CP16(st + MAT_A + SWOFF(row, ch), \
                 g_w216 + ((size_t)e * D_DIM + d0 + row) * F_DIM + k0 + ch * 8); \
        } } while (0)

    G2_ISSUE(0, 0); CP_COMMIT();
    G2_ISSUE(1, 1); CP_COMMIT();
    G2_ISSUE(2, 2); CP_COMMIT();

    #pragma unroll 1
    for (int c = 0; c < NCHUNK; c++) {
        CP_WAIT2();
        __syncthreads();
        if (c + 3 < NCHUNK) G2_ISSUE(c + 3, (c + 3) & 3);
        CP_COMMIT();
        MMA_COMPUTE(sb + (c & 3) * STAGE);
    }
    #undef G2_ISSUE

    // epilogue: bias + fp32 y (quad-coalesced 32B segments)
    #pragma unroll
    for (int mt = 0; mt < 4; mt++) {
        #pragma unroll
        for (int dd = 0; dd < 2; dd++) {
            int lrow = warp_m * 64 + mt * 16 + dd * 8 + (lane >> 2);
            if (row0 + lrow >= cnt) continue;
            float* yrow = g_y + ((size_t)e * CAP + row0 + lrow) * D_DIM;
            #pragma unroll
            for (int nt = 0; nt < 8; nt++) {
                int col = d0 + warp_n * 64 + nt * 8 + (lane & 3) * 2;
                float2 o;
                o.x = acc[mt][nt][dd * 2]     + b2[e * D_DIM + col];
                o.y = acc[mt][nt][dd * 2 + 1] + b2[e * D_DIM + col + 1];
                *(float2*)(yrow + col) = o;
            }
        }
    }
}

// ---------------- kernel 4: deterministic weighted combine ----------------
__global__ void combine_kernel(float* __restrict__ out) {
    int t = blockIdx.x;
    int   e0 = g_t2e[t * 2 + 0], e1 = g_t2e[t * 2 + 1];
    float w0 = g_t2w[t * 2 + 0], w1 = g_t2w[t * 2 + 1];
    const float* y0 = g_y + (size_t)e0 * D_DIM;
    const float* y1 = g_y + (size_t)e1 * D_DIM;
    float* o = out + (size_t)t * D_DIM;
    for (int d = threadIdx.x; d < D_DIM; d += blockDim.x)
        o[d] = w0 * y0[d] + w1 * y1[d];
}

extern "C" void kernel_launch(void* const* d_in, const int* in_sizes, int n_in,
                              void* d_out, int out_size) {
    const float* x  = (const float*)d_in[0];
    const float* gw = (const float*)d_in[1];
    const float* w1 = (const float*)d_in[2];
    const float* b1 = (const float*)d_in[3];
    const float* w2 = (const float*)d_in[4];
    const float* b2 = (const float*)d_in[5];
    float* out = (float*)d_out;

    static int configured = 0;
    if (!configured) {
        cudaFuncSetAttribute(ffn1_mma, cudaFuncAttributeMaxDynamicSharedMemorySize, SMEM_BYTES);
        cudaFuncSetAttribute(ffn2_mma, cudaFuncAttributeMaxDynamicSharedMemorySize, SMEM_BYTES);
        configured = 1;
    }

    __half *x16, *w116, *w216;
    cudaGetSymbolAddress((void**)&x16,  g_x16);
    cudaGetSymbolAddress((void**)&w116, g_w116);
    cudaGetSymbolAddress((void**)&w216, g_w216);

    zero_cnt_kernel<<<1, 32>>>();
    gate_kernel<<<T_TOK, 256>>>(x, gw);
    cvt_kernel<<<2048, 256>>>(x,  x16,  (T_TOK * D_DIM) / 4);
    cvt_kernel<<<8192, 256>>>(w1, w116, (E_NUM * F2 * D_DIM) / 4);
    cvt_kernel<<<8192, 256>>>(w2, w216, (E_NUM * D_DIM * F_DIM) / 4);
    ffn1_mma<<<dim3(F2 / BN, CAP / BM, E_NUM), 256, SMEM_BYTES>>>(b1);
    ffn2_mma<<<dim3(D_DIM / BN, CAP / BM, E_NUM), 256, SMEM_BYTES>>>(b2);
    combine_kernel<<<T_TOK, 256>>>(out);
}

// round 13
// speedup vs baseline: 1.2326x; 1.2326x over previous
#include <cuda_runtime.h>
#include <cuda_fp16.h>
#include <math.h>
#include <stdint.h>

// Problem constants
#define T_TOK 4096
#define D_DIM 1024
#define E_NUM 8
#define F_DIM 2048
#define F2    4096
#define CAP   4096

// Tile config (R8 shape): CTA 128x128x64, 8 warps (4m x 2n), warp tile 32x64
#define BM 128
#define BN 128
#define BK 64
#define MAT   16384                   // one operand tile: 128 rows x 128B (pre-swizzled)
#define STAGE (2 * MAT)               // A + B = 32768
#define NSTAGE 3
#define SMEM_BYTES (NSTAGE * STAGE)   // 98304 -> 2 CTAs/SM

// ---------------- scratch (device globals; no allocs allowed) ----------------
__device__ int   g_cnt[E_NUM];
__device__ int   g_tok[E_NUM * CAP];
__device__ int   g_t2e[T_TOK * 2];
__device__ float g_t2w[T_TOK * 2];
// tiled, SW128-pre-swizzled fp16 operand buffers (16KB tiles, kc innermost)
__device__ __align__(16) __half g_A1[(size_t)E_NUM * 32 * 16 * 8192];  // x gathered  [e][mt][kc]   67MB
__device__ __align__(16) __half g_B1[(size_t)E_NUM * 32 * 16 * 8192];  // w1          [e][nt][kc]   67MB
__device__ __align__(16) __half g_A2[(size_t)E_NUM * 32 * 32 * 8192];  // H           [e][mt][kc]  134MB
__device__ __align__(16) __half g_B2[(size_t)E_NUM * 8  * 32 * 8192];  // w2          [e][dt][kc]   34MB
__device__ float g_y[(size_t)E_NUM * CAP * D_DIM];                     // 134MB

// ---------------- helpers ----------------
__device__ __forceinline__ uint32_t smem_u32(const void* p) {
    uint32_t a;
    asm("{ .reg .u64 t; cvta.to.shared.u64 t, %1; cvt.u32.u64 %0, t; }" : "=r"(a) : "l"(p));
    return a;
}
__device__ __forceinline__ void ldsm_x4(uint32_t& r0, uint32_t& r1, uint32_t& r2, uint32_t& r3,
                                        uint32_t addr) {
    asm volatile("ldmatrix.sync.aligned.m8n8.x4.shared.b16 {%0,%1,%2,%3}, [%4];"
                 : "=r"(r0), "=r"(r1), "=r"(r2), "=r"(r3) : "r"(addr));
}
__device__ __forceinline__ void mma_f16(float* c,
                                        uint32_t a0, uint32_t a1, uint32_t a2, uint32_t a3,
                                        uint32_t b0, uint32_t b1) {
    asm volatile("mma.sync.aligned.m16n8k16.row.col.f32.f16.f16.f32 "
                 "{%0,%1,%2,%3}, {%4,%5,%6,%7}, {%8,%9}, {%0,%1,%2,%3};"
                 : "+f"(c[0]), "+f"(c[1]), "+f"(c[2]), "+f"(c[3])
                 : "r"(a0), "r"(a1), "r"(a2), "r"(a3), "r"(b0), "r"(b1));
}
#define MBAR_INIT(a, c) \
    asm volatile("mbarrier.init.shared.b64 [%0], %1;" :: "r"(a), "r"(c) : "memory")
#define MBAR_EXPECT(a, tx) \
    asm volatile("mbarrier.arrive.expect_tx.shared.b64 _, [%0], %1;" :: "r"(a), "r"(tx) : "memory")
#define BULK16K(dst, src, mbar) \
    asm volatile("cp.async.bulk.shared::cluster.global.mbarrier::complete_tx::bytes [%0], [%1], 16384, [%2];" \
                 :: "r"(dst), "l"(src), "r"(mbar) : "memory")
#define MBAR_WAIT(addr, par) do { \
    uint32_t _m = (addr), _p = (par), _d; \
    asm volatile("{ .reg .pred p; mbarrier.try_wait.parity.acquire.cta.shared::cta.b64 p, [%1], %2; selp.b32 %0, 1, 0, p; }" \
        : "=r"(_d) : "r"(_m), "r"(_p) : "memory"); \
    if (!_d) { \
        asm volatile("{ .reg .pred P1; WL_%=: mbarrier.try_wait.parity.acquire.cta.shared::cta.b64 P1, [%0], %1, 0x989680; @P1 bra.uni WD_%=; bra.uni WL_%=; WD_%=: }" \
            :: "r"(_m), "r"(_p) : "memory"); \
    } } while (0)

// pack 8 fp32 -> 8 fp16 (16B)
__device__ __forceinline__ uint4 pack8(float4 a, float4 b) {
    __half2 h0 = __floats2half2_rn(a.x, a.y);
    __half2 h1 = __floats2half2_rn(a.z, a.w);
    __half2 h2 = __floats2half2_rn(b.x, b.y);
    __half2 h3 = __floats2half2_rn(b.z, b.w);
    uint4 r;
    r.x = *(uint32_t*)&h0; r.y = *(uint32_t*)&h1;
    r.z = *(uint32_t*)&h2; r.w = *(uint32_t*)&h3;
    return r;
}

// ---------------- kernel 0: reset counters ----------------
__global__ void zero_cnt_kernel() {
    if (threadIdx.x < E_NUM) g_cnt[threadIdx.x] = 0;
}

// ---------------- kernel 1: gating + top-2 routing (fp32, exact) ----------------
__global__ void gate_kernel(const float* __restrict__ x,
                            const float* __restrict__ gw) {
    int t = blockIdx.x;
    __shared__ float xs[D_DIM];
    __shared__ float gates[E_NUM];
    int tid = threadIdx.x;
    for (int i = tid; i < D_DIM; i += blockDim.x)
        xs[i] = x[(size_t)t * D_DIM + i];
    __syncthreads();
    int wid = tid >> 5, lane = tid & 31;
    float s = 0.f;
    for (int d = lane; d < D_DIM; d += 32)
        s += xs[d] * gw[d * E_NUM + wid];
    #pragma unroll
    for (int o = 16; o > 0; o >>= 1)
        s += __shfl_down_sync(0xffffffffu, s, o);
    if (lane == 0) gates[wid] = s;
    __syncthreads();
    if (tid == 0) {
        int i0 = 0; float g0 = gates[0];
        #pragma unroll
        for (int e = 1; e < E_NUM; e++)
            if (gates[e] > g0) { g0 = gates[e]; i0 = e; }
        int i1 = -1; float g1 = -1e30f;
        #pragma unroll
        for (int e = 0; e < E_NUM; e++)
            if (e != i0 && gates[e] > g1) { g1 = gates[e]; i1 = e; }
        float ex = expf(g1 - g0);
        float w0 = 1.f / (1.f + ex);
        float w1 = ex / (1.f + ex);
        int s0 = atomicAdd(&g_cnt[i0], 1);
        int s1 = atomicAdd(&g_cnt[i1], 1);
        g_tok[i0 * CAP + s0] = t;
        g_tok[i1 * CAP + s1] = t;
        g_t2e[t * 2 + 0] = i0 * CAP + s0;
        g_t2e[t * 2 + 1] = i1 * CAP + s1;
        g_t2w[t * 2 + 0] = w0;
        g_t2w[t * 2 + 1] = w1;
    }
}

// ---------------- kernel 2: gather x rows into tiled swizzled g_A1 ----------------
// 2 rows per block of 256; 128 threads per row, one 16B chunk each.
__global__ void gatherA1_kernel(const float* __restrict__ x) {
    int tid = threadIdx.x;
    int r = blockIdx.x * 2 + (tid >> 7);      // global slot index over [E_NUM*CAP)
    int e = r >> 12, slot = r & (CAP - 1);
    if (slot >= g_cnt[e]) return;             // pad slots stay zero
    int tok = g_tok[r];
    int t = tid & 127;
    const float4* src = (const float4*)(x + (size_t)tok * D_DIM + t * 8);
    uint4 v = pack8(src[0], src[1]);
    int kc = t >> 3, ch = t & 7;
    size_t dstB = ((size_t)((e * 32 + (slot >> 7)) * 16 + kc)) * 16384
                + (slot & 127) * 128 + ((ch * 16) ^ ((slot & 7) << 4));
    *(uint4*)((char*)g_A1 + dstB) = v;
}

// ---------------- kernel 3: w1 fp32 -> tiled swizzled fp16 g_B1 ----------------
__global__ void cvtW1_kernel(const float* __restrict__ w1) {
    const int NCH = E_NUM * F2 * (D_DIM / 8);   // 4.19M chunks
    int i = blockIdx.x * blockDim.x + threadIdx.x;
    int stride = gridDim.x * blockDim.x;
    for (; i < NCH; i += stride) {
        int row = i >> 7, t = i & 127;          // row over e*F2+n
        const float4* src = (const float4*)(w1 + (size_t)row * D_DIM + t * 8);
        uint4 v = pack8(src[0], src[1]);
        int e = row >> 12, n = row & 4095;
        int nt = n >> 7, nr = n & 127;
        int kc = t >> 3, ch = t & 7;
        size_t dstB = ((size_t)((e * 32 + nt) * 16 + kc)) * 16384
                    + nr * 128 + ((ch * 16) ^ ((nr & 7) << 4));
        *(uint4*)((char*)g_B1 + dstB) = v;
    }
}

// ---------------- kernel 4: w2 fp32 -> tiled swizzled fp16 g_B2 ----------------
__global__ void cvtW2_kernel(const float* __restrict__ w2) {
    const int NCH = E_NUM * D_DIM * (F_DIM / 8);  // 2.1M chunks
    int i = blockIdx.x * blockDim.x + threadIdx.x;
    int stride = gridDim.x * blockDim.x;
    for (; i < NCH; i += stride) {
        int row = i >> 8, t = i & 255;            // row over e*D+d
        const float4* src = (const float4*)(w2 + (size_t)row * F_DIM + t * 8);
        uint4 v = pack8(src[0], src[1]);
        int e = row >> 10, d = row & 1023;
        int dt = d >> 7, dr = d & 127;
        int kc = t >> 3, ch = t & 7;
        size_t dstB = ((size_t)((e * 8 + dt) * 32 + kc)) * 16384
                    + dr * 128 + ((ch * 16) ^ ((dr & 7) << 4));
        *(uint4*)((char*)g_B2 + dstB) = v;
    }
}

// ======================================================================
// GEMMs: bulk-copy mbarrier pipeline, LDSM offsets identical to R8.
// ======================================================================

#define LDSM_OFFSETS() \
    const int lj = lane >> 3, lr = lane & 7; \
    int a_row[2], a_sw[2], b_row[4], b_sw[4]; \
    const int a_chb = (lj >> 1) * 16; \
    const int b_chb = (lj & 1) * 16; \
    _Pragma("unroll") \
    for (int mt = 0; mt < 2; mt++) { \
        int ra = warp_m * 32 + mt * 16 + (lj & 1) * 8 + lr; \
        a_row[mt] = ra * 128; a_sw[mt] = (ra & 7) << 4; \
    } \
    _Pragma("unroll") \
    for (int np = 0; np < 4; np++) { \
        int rb = warp_n * 64 + np * 16 + (lj >> 1) * 8 + lr; \
        b_row[np] = rb * 128; b_sw[np] = (rb & 7) << 4; \
    }

#define MMA_COMPUTE(base) do { \
    _Pragma("unroll") \
    for (int kk = 0; kk < 4; kk++) { \
        uint32_t af[2][4]; \
        _Pragma("unroll") \
        for (int mt = 0; mt < 2; mt++) \
            ldsm_x4(af[mt][0], af[mt][1], af[mt][2], af[mt][3], \
                    (base) + a_row[mt] + ((kk * 32 + a_chb) ^ a_sw[mt])); \
        _Pragma("unroll") \
        for (int np = 0; np < 4; np++) { \
            uint32_t bf[4]; \
            ldsm_x4(bf[0], bf[1], bf[2], bf[3], \
                    (base) + MAT + b_row[np] + ((kk * 32 + b_chb) ^ b_sw[np])); \
            _Pragma("unroll") \
            for (int mt = 0; mt < 2; mt++) { \
                mma_f16(acc[mt][2 * np],     af[mt][0], af[mt][1], af[mt][2], af[mt][3], bf[0], bf[1]); \
                mma_f16(acc[mt][2 * np + 1], af[mt][0], af[mt][1], af[mt][2], af[mt][3], bf[2], bf[3]); \
            } \
        } \
    } } while (0)

#define GEMM_PIPELINE(NCHUNK, Asrc, Bsrc) do { \
    if (tid == 0) { \
        _Pragma("unroll") \
        for (int s = 0; s < NSTAGE; s++) MBAR_INIT(mb + 8 * s, 1); \
    } \
    __syncthreads(); \
    if (tid == 0) { \
        _Pragma("unroll") \
        for (int s = 0; s < NSTAGE; s++) { \
            MBAR_EXPECT(mb + 8 * s, 2 * MAT); \
            BULK16K(sb + s * STAGE,       (Asrc) + (size_t)s * MAT, mb + 8 * s); \
            BULK16K(sb + s * STAGE + MAT, (Bsrc) + (size_t)s * MAT, mb + 8 * s); \
        } \
    } \
    _Pragma("unroll 1") \
    for (int c = 0; c < (NCHUNK); c++) { \
        int s = c % 3; \
        MBAR_WAIT(mb + 8 * s, (c / 3) & 1); \
        MMA_COMPUTE(sb + s * STAGE); \
        __syncthreads(); \
        if (tid == 0 && c + 3 < (NCHUNK)) { \
            MBAR_EXPECT(mb + 8 * s, 2 * MAT); \
            BULK16K(sb + s * STAGE,       (Asrc) + (size_t)(c + 3) * MAT, mb + 8 * s); \
            BULK16K(sb + s * STAGE + MAT, (Bsrc) + (size_t)(c + 3) * MAT, mb + 8 * s); \
        } \
    } } while (0)

// ---------------- kernel 5: GEMM1 + SwiGLU -> tiled H (g_A2) ----------------
__global__ void __launch_bounds__(256, 2) ffn1_mma(const float* __restrict__ b1) {
    extern __shared__ char smem[];
    __shared__ __align__(8) uint64_t mbars[NSTAGE];
    const int e = blockIdx.z;
    const int cnt = g_cnt[e];
    const int row0 = blockIdx.y * BM;
    if (row0 >= cnt) return;
    const int bx = blockIdx.x;

    const int tid = threadIdx.x;
    const int lane = tid & 31;
    const int warp_m = (tid >> 5) & 3;
    const int warp_n = tid >> 7;
    const uint32_t sb = smem_u32(smem), mb = smem_u32(mbars);

    const char* Asrc = (const char*)g_A1 + ((size_t)((e * 32 + blockIdx.y) * 16)) * 16384;
    const char* Bsrc = (const char*)g_B1 + ((size_t)((e * 32 + bx) * 16)) * 16384;

    LDSM_OFFSETS();
    float acc[2][8][4];
    #pragma unroll
    for (int i = 0; i < 2; i++)
        #pragma unroll
        for (int j = 0; j < 8; j++)
            #pragma unroll
            for (int k = 0; k < 4; k++) acc[i][j][k] = 0.f;

    GEMM_PIPELINE(16, Asrc, Bsrc);

    // epilogue: bias + SwiGLU -> swizzled smem tile -> one contiguous 16KB store
    char* hsb = smem;
    #pragma unroll
    for (int mt = 0; mt < 2; mt++) {
        #pragma unroll
        for (int dd = 0; dd < 2; dd++) {
            int lrow = warp_m * 32 + mt * 16 + dd * 8 + (lane >> 2);
            #pragma unroll
            for (int nt = 0; nt < 8; nt++) {
                int colp = bx * BN + warp_n * 64 + nt * 8 + (lane & 3) * 2;
                float g = acc[mt][nt][dd * 2]     + b1[e * F2 + colp];
                float v = acc[mt][nt][dd * 2 + 1] + b1[e * F2 + colp + 1];
                g = fminf(g, 9.0f);
                v = fmaxf(fminf(v, 9.0f), -9.0f);
                float sig = 1.0f / (1.0f + __expf(-1.702f * g));
                float h = g * sig * (v + 1.0f);
                int hcol = warp_n * 32 + nt * 4 + (lane & 3);
                *(__half*)(hsb + lrow * 128 + ((hcol * 2) ^ ((lrow & 7) << 4))) =
                    __float2half_rn(h);
            }
        }
    }
    __syncthreads();
    uint4* dst = (uint4*)((char*)g_A2 + ((size_t)((e * 32 + blockIdx.y) * 32 + bx)) * 16384);
    const uint4* s4 = (const uint4*)hsb;
    #pragma unroll
    for (int j = 0; j < 4; j++)
        dst[tid + 256 * j] = s4[tid + 256 * j];
}

// ---------------- kernel 6: GEMM2 (y = H @ W2^T + b2) ----------------
__global__ void __launch_bounds__(256, 2) ffn2_mma(const float* __restrict__ b2) {
    extern __shared__ char smem[];
    __shared__ __align__(8) uint64_t mbars[NSTAGE];
    const int e = blockIdx.z;
    const int cnt = g_cnt[e];
    const int row0 = blockIdx.y * BM;
    if (row0 >= cnt) return;
    const int bx = blockIdx.x;

    const int tid = threadIdx.x;
    const int lane = tid & 31;
    const int warp_m = (tid >> 5) & 3;
    const int warp_n = tid >> 7;
    const uint32_t sb = smem_u32(smem), mb = smem_u32(mbars);

    const char* Asrc = (const char*)g_A2 + ((size_t)((e * 32 + blockIdx.y) * 32)) * 16384;
    const char* Bsrc = (const char*)g_B2 + ((size_t)((e * 8 + bx) * 32)) * 16384;

    LDSM_OFFSETS();
    float acc[2][8][4];
    #pragma unroll
    for (int i = 0; i < 2; i++)
        #pragma unroll
        for (int j = 0; j < 8; j++)
            #pragma unroll
            for (int k = 0; k < 4; k++) acc[i][j][k] = 0.f;

    GEMM_PIPELINE(32, Asrc, Bsrc);

    // epilogue: bias + fp32 y
    #pragma unroll
    for (int mt = 0; mt < 2; mt++) {
        #pragma unroll
        for (int dd = 0; dd < 2; dd++) {
            int lrow = warp_m * 32 + mt * 16 + dd * 8 + (lane >> 2);
            if (row0 + lrow >= cnt) continue;
            float* yrow = g_y + ((size_t)e * CAP + row0 + lrow) * D_DIM;
            #pragma unroll
            for (int nt = 0; nt < 8; nt++) {
                int col = bx * BN + warp_n * 64 + nt * 8 + (lane & 3) * 2;
                float2 o;
                o.x = acc[mt][nt][dd * 2]     + b2[e * D_DIM + col];
                o.y = acc[mt][nt][dd * 2 + 1] + b2[e * D_DIM + col + 1];
                *(float2*)(yrow + col) = o;
            }
        }
    }
}

// ---------------- kernel 7: deterministic weighted combine ----------------
__global__ void combine_kernel(float* __restrict__ out) {
    int t = blockIdx.x;
    int   e0 = g_t2e[t * 2 + 0], e1 = g_t2e[t * 2 + 1];
    float w0 = g_t2w[t * 2 + 0], w1 = g_t2w[t * 2 + 1];
    const float* y0 = g_y + (size_t)e0 * D_DIM;
    const float* y1 = g_y + (size_t)e1 * D_DIM;
    float* o = out + (size_t)t * D_DIM;
    for (int d = threadIdx.x; d < D_DIM; d += blockDim.x)
        o[d] = w0 * y0[d] + w1 * y1[d];
}

extern "C" void kernel_launch(void* const* d_in, const int* in_sizes, int n_in,
                              void* d_out, int out_size) {
    const float* x  = (const float*)d_in[0];
    const float* gw = (const float*)d_in[1];
    const float* w1 = (const float*)d_in[2];
    const float* b1 = (const float*)d_in[3];
    const float* w2 = (const float*)d_in[4];
    const float* b2 = (const float*)d_in[5];
    float* out = (float*)d_out;

    static int configured = 0;
    if (!configured) {
        cudaFuncSetAttribute(ffn1_mma, cudaFuncAttributeMaxDynamicSharedMemorySize, SMEM_BYTES);
        cudaFuncSetAttribute(ffn2_mma, cudaFuncAttributeMaxDynamicSharedMemorySize, SMEM_BYTES);
        configured = 1;
    }

    zero_cnt_kernel<<<1, 32>>>();
    gate_kernel<<<T_TOK, 256>>>(x, gw);
    gatherA1_kernel<<<E_NUM * CAP / 2, 256>>>(x);
    cvtW1_kernel<<<8192, 256>>>(w1);
    cvtW2_kernel<<<4096, 256>>>(w2);
    ffn1_mma<<<dim3(F2 / BN, CAP / BM, E_NUM), 256, SMEM_BYTES>>>(b1);
    ffn2_mma<<<dim3(D_DIM / BN, CAP / BM, E_NUM), 256, SMEM_BYTES>>>(b2);
    combine_kernel<<<T_TOK, 256>>>(out);
}

// round 14
// speedup vs baseline: 1.2811x; 1.0393x over previous
#include <cuda_runtime.h>
#include <cuda_fp16.h>
#include <math.h>
#include <stdint.h>

// Problem constants
#define T_TOK 4096
#define D_DIM 1024
#define E_NUM 8
#define F_DIM 2048
#define F2    4096
#define CAP   4096

// Tile config: CTA 128x128x64, 8 warps (4m x 2n), warp tile 32x64
#define BM 128
#define BN 128
#define BK 64
#define MAT   16384                   // one operand tile: 128 rows x 128B (pre-swizzled)
#define STAGE (2 * MAT)               // A + B = 32768
#define NSTAGE 3
#define SMEM_BYTES (NSTAGE * STAGE)   // 98304 -> 2 CTAs/SM

// ---------------- scratch (device globals; no allocs allowed) ----------------
__device__ int   g_cnt[E_NUM];
__device__ int   g_t2e[T_TOK * 2];
__device__ float g_t2w[T_TOK * 2];
// tiled, SW128-pre-swizzled fp16 operand buffers (16KB tiles, kc innermost)
__device__ __align__(16) __half g_A1[(size_t)E_NUM * 32 * 16 * 8192];  // x gathered  [e][mt][kc]
__device__ __align__(16) __half g_B1[(size_t)E_NUM * 32 * 16 * 8192];  // w1          [e][nt][kc]
__device__ __align__(16) __half g_A2[(size_t)E_NUM * 32 * 32 * 8192];  // H           [e][mt][kc]
__device__ __align__(16) __half g_B2[(size_t)E_NUM * 8  * 32 * 8192];  // w2          [e][dt][kc]
__device__ float g_y[(size_t)E_NUM * CAP * D_DIM];

// ---------------- helpers ----------------
__device__ __forceinline__ uint32_t smem_u32(const void* p) {
    uint32_t a;
    asm("{ .reg .u64 t; cvta.to.shared.u64 t, %1; cvt.u32.u64 %0, t; }" : "=r"(a) : "l"(p));
    return a;
}
__device__ __forceinline__ void ldsm_x4(uint32_t& r0, uint32_t& r1, uint32_t& r2, uint32_t& r3,
                                        uint32_t addr) {
    asm volatile("ldmatrix.sync.aligned.m8n8.x4.shared.b16 {%0,%1,%2,%3}, [%4];"
                 : "=r"(r0), "=r"(r1), "=r"(r2), "=r"(r3) : "r"(addr));
}
__device__ __forceinline__ void mma_f16(float* c,
                                        uint32_t a0, uint32_t a1, uint32_t a2, uint32_t a3,
                                        uint32_t b0, uint32_t b1) {
    asm volatile("mma.sync.aligned.m16n8k16.row.col.f32.f16.f16.f32 "
                 "{%0,%1,%2,%3}, {%4,%5,%6,%7}, {%8,%9}, {%0,%1,%2,%3};"
                 : "+f"(c[0]), "+f"(c[1]), "+f"(c[2]), "+f"(c[3])
                 : "r"(a0), "r"(a1), "r"(a2), "r"(a3), "r"(b0), "r"(b1));
}
#define MBAR_INIT(a, c) \
    asm volatile("mbarrier.init.shared.b64 [%0], %1;" :: "r"(a), "r"(c) : "memory")
#define MBAR_EXPECT(a, tx) \
    asm volatile("mbarrier.arrive.expect_tx.shared.b64 _, [%0], %1;" :: "r"(a), "r"(tx) : "memory")
#define BULK16K(dst, src, mbar) \
    asm volatile("cp.async.bulk.shared::cluster.global.mbarrier::complete_tx::bytes [%0], [%1], 16384, [%2];" \
                 :: "r"(dst), "l"(src), "r"(mbar) : "memory")
#define MBAR_WAIT(addr, par) do { \
    uint32_t _m = (addr), _p = (par), _d; \
    asm volatile("{ .reg .pred p; mbarrier.try_wait.parity.acquire.cta.shared::cta.b64 p, [%1], %2; selp.b32 %0, 1, 0, p; }" \
        : "=r"(_d) : "r"(_m), "r"(_p) : "memory"); \
    if (!_d) { \
        asm volatile("{ .reg .pred P1; WL_%=: mbarrier.try_wait.parity.acquire.cta.shared::cta.b64 P1, [%0], %1, 0x989680; @P1 bra.uni WD_%=; bra.uni WL_%=; WD_%=: }" \
            :: "r"(_m), "r"(_p) : "memory"); \
    } } while (0)

// pack 8 fp32 -> 8 fp16 (16B)
__device__ __forceinline__ uint4 pack8(float4 a, float4 b) {
    __half2 h0 = __floats2half2_rn(a.x, a.y);
    __half2 h1 = __floats2half2_rn(a.z, a.w);
    __half2 h2 = __floats2half2_rn(b.x, b.y);
    __half2 h3 = __floats2half2_rn(b.z, b.w);
    uint4 r;
    r.x = *(uint32_t*)&h0; r.y = *(uint32_t*)&h1;
    r.z = *(uint32_t*)&h2; r.w = *(uint32_t*)&h3;
    return r;
}

// ---------------- kernel 0: reset counters ----------------
__global__ void zero_cnt_kernel() {
    if (threadIdx.x < E_NUM) g_cnt[threadIdx.x] = 0;
}

// ---------------- kernel 1: gating + top-2 routing + FUSED x gather ----------------
__global__ void gate_kernel(const float* __restrict__ x,
                            const float* __restrict__ gw) {
    int t = blockIdx.x;
    __shared__ float xs[D_DIM];
    __shared__ float gates[E_NUM];
    __shared__ int   sel_e[2], sel_slot[2];
    int tid = threadIdx.x;
    for (int i = tid; i < D_DIM; i += blockDim.x)
        xs[i] = x[(size_t)t * D_DIM + i];
    __syncthreads();
    int wid = tid >> 5, lane = tid & 31;
    float s = 0.f;
    for (int d = lane; d < D_DIM; d += 32)
        s += xs[d] * gw[d * E_NUM + wid];
    #pragma unroll
    for (int o = 16; o > 0; o >>= 1)
        s += __shfl_down_sync(0xffffffffu, s, o);
    if (lane == 0) gates[wid] = s;
    __syncthreads();
    if (tid == 0) {
        int i0 = 0; float g0 = gates[0];
        #pragma unroll
        for (int e = 1; e < E_NUM; e++)
            if (gates[e] > g0) { g0 = gates[e]; i0 = e; }
        int i1 = -1; float g1 = -1e30f;
        #pragma unroll
        for (int e = 0; e < E_NUM; e++)
            if (e != i0 && gates[e] > g1) { g1 = gates[e]; i1 = e; }
        float ex = expf(g1 - g0);
        float w0 = 1.f / (1.f + ex);
        float w1 = ex / (1.f + ex);
        int s0 = atomicAdd(&g_cnt[i0], 1);
        int s1 = atomicAdd(&g_cnt[i1], 1);
        sel_e[0] = i0; sel_slot[0] = s0;
        sel_e[1] = i1; sel_slot[1] = s1;
        g_t2e[t * 2 + 0] = i0 * CAP + s0;
        g_t2e[t * 2 + 1] = i1 * CAP + s1;
        g_t2w[t * 2 + 0] = w0;
        g_t2w[t * 2 + 1] = w1;
    }
    __syncthreads();
    // write this token's fp16 row into both experts' tiled A1 buffers
    int k = tid >> 7;            // entry 0 or 1
    int tt = tid & 127;          // 16B chunk within the row
    int e = sel_e[k], slot = sel_slot[k];
    float4 a = *(const float4*)(xs + tt * 8);
    float4 b = *(const float4*)(xs + tt * 8 + 4);
    uint4 v = pack8(a, b);
    int kc = tt >> 3, ch = tt & 7;
    size_t dstB = ((size_t)((e * 32 + (slot >> 7)) * 16 + kc)) * 16384
                + (slot & 127) * 128 + ((ch * 16) ^ ((slot & 7) << 4));
    *(uint4*)((char*)g_A1 + dstB) = v;
}

// ---------------- kernel 2: w1 fp32 -> tiled swizzled fp16 g_B1 ----------------
__global__ void cvtW1_kernel(const float* __restrict__ w1) {
    const int NCH = E_NUM * F2 * (D_DIM / 8);
    int i = blockIdx.x * blockDim.x + threadIdx.x;
    int stride = gridDim.x * blockDim.x;
    for (; i < NCH; i += stride) {
        int row = i >> 7, t = i & 127;
        const float4* src = (const float4*)(w1 + (size_t)row * D_DIM + t * 8);
        uint4 v = pack8(src[0], src[1]);
        int e = row >> 12, n = row & 4095;
        int nt = n >> 7, nr = n & 127;
        int kc = t >> 3, ch = t & 7;
        size_t dstB = ((size_t)((e * 32 + nt) * 16 + kc)) * 16384
                    + nr * 128 + ((ch * 16) ^ ((nr & 7) << 4));
        *(uint4*)((char*)g_B1 + dstB) = v;
    }
}

// ---------------- kernel 3: w2 fp32 -> tiled swizzled fp16 g_B2 ----------------
__global__ void cvtW2_kernel(const float* __restrict__ w2) {
    const int NCH = E_NUM * D_DIM * (F_DIM / 8);
    int i = blockIdx.x * blockDim.x + threadIdx.x;
    int stride = gridDim.x * blockDim.x;
    for (; i < NCH; i += stride) {
        int row = i >> 8, t = i & 255;
        const float4* src = (const float4*)(w2 + (size_t)row * F_DIM + t * 8);
        uint4 v = pack8(src[0], src[1]);
        int e = row >> 10, d = row & 1023;
        int dt = d >> 7, dr = d & 127;
        int kc = t >> 3, ch = t & 7;
        size_t dstB = ((size_t)((e * 8 + dt) * 32 + kc)) * 16384
                    + dr * 128 + ((ch * 16) ^ ((dr & 7) << 4));
        *(uint4*)((char*)g_B2 + dstB) = v;
    }
}

// ======================================================================
// GEMMs: bulk-copy mbarrier pipeline (unchanged from R13).
// ======================================================================

#define LDSM_OFFSETS() \
    const int lj = lane >> 3, lr = lane & 7; \
    int a_row[2], a_sw[2], b_row[4], b_sw[4]; \
    const int a_chb = (lj >> 1) * 16; \
    const int b_chb = (lj & 1) * 16; \
    _Pragma("unroll") \
    for (int mt = 0; mt < 2; mt++) { \
        int ra = warp_m * 32 + mt * 16 + (lj & 1) * 8 + lr; \
        a_row[mt] = ra * 128; a_sw[mt] = (ra & 7) << 4; \
    } \
    _Pragma("unroll") \
    for (int np = 0; np < 4; np++) { \
        int rb = warp_n * 64 + np * 16 + (lj >> 1) * 8 + lr; \
        b_row[np] = rb * 128; b_sw[np] = (rb & 7) << 4; \
    }

#define MMA_COMPUTE(base) do { \
    _Pragma("unroll") \
    for (int kk = 0; kk < 4; kk++) { \
        uint32_t af[2][4]; \
        _Pragma("unroll") \
        for (int mt = 0; mt < 2; mt++) \
            ldsm_x4(af[mt][0], af[mt][1], af[mt][2], af[mt][3], \
                    (base) + a_row[mt] + ((kk * 32 + a_chb) ^ a_sw[mt])); \
        _Pragma("unroll") \
        for (int np = 0; np < 4; np++) { \
            uint32_t bf[4]; \
            ldsm_x4(bf[0], bf[1], bf[2], bf[3], \
                    (base) + MAT + b_row[np] + ((kk * 32 + b_chb) ^ b_sw[np])); \
            _Pragma("unroll") \
            for (int mt = 0; mt < 2; mt++) { \
                mma_f16(acc[mt][2 * np],     af[mt][0], af[mt][1], af[mt][2], af[mt][3], bf[0], bf[1]); \
                mma_f16(acc[mt][2 * np + 1], af[mt][0], af[mt][1], af[mt][2], af[mt][3], bf[2], bf[3]); \
            } \
        } \
    } } while (0)

#define GEMM_PIPELINE(NCHUNK, Asrc, Bsrc) do { \
    if (tid == 0) { \
        _Pragma("unroll") \
        for (int s = 0; s < NSTAGE; s++) MBAR_INIT(mb + 8 * s, 1); \
    } \
    __syncthreads(); \
    if (tid == 0) { \
        _Pragma("unroll") \
        for (int s = 0; s < NSTAGE; s++) { \
            MBAR_EXPECT(mb + 8 * s, 2 * MAT); \
            BULK16K(sb + s * STAGE,       (Asrc) + (size_t)s * MAT, mb + 8 * s); \
            BULK16K(sb + s * STAGE + MAT, (Bsrc) + (size_t)s * MAT, mb + 8 * s); \
        } \
    } \
    _Pragma("unroll 1") \
    for (int c = 0; c < (NCHUNK); c++) { \
        int s = c % 3; \
        MBAR_WAIT(mb + 8 * s, (c / 3) & 1); \
        MMA_COMPUTE(sb + s * STAGE); \
        __syncthreads(); \
        if (tid == 0 && c + 3 < (NCHUNK)) { \
            MBAR_EXPECT(mb + 8 * s, 2 * MAT); \
            BULK16K(sb + s * STAGE,       (Asrc) + (size_t)(c + 3) * MAT, mb + 8 * s); \
            BULK16K(sb + s * STAGE + MAT, (Bsrc) + (size_t)(c + 3) * MAT, mb + 8 * s); \
        } \
    } } while (0)

// ---------------- kernel 4: GEMM1 + SwiGLU -> tiled H (g_A2) ----------------
__global__ void __launch_bounds__(256, 2) ffn1_mma(const float* __restrict__ b1) {
    extern __shared__ char smem[];
    __shared__ __align__(8) uint64_t mbars[NSTAGE];
    const int e = blockIdx.z;
    const int cnt = g_cnt[e];
    const int row0 = blockIdx.y * BM;
    if (row0 >= cnt) return;
    const int bx = blockIdx.x;

    const int tid = threadIdx.x;
    const int lane = tid & 31;
    const int warp_m = (tid >> 5) & 3;
    const int warp_n = tid >> 7;
    const uint32_t sb = smem_u32(smem), mb = smem_u32(mbars);

    const char* Asrc = (const char*)g_A1 + ((size_t)((e * 32 + blockIdx.y) * 16)) * 16384;
    const char* Bsrc = (const char*)g_B1 + ((size_t)((e * 32 + bx) * 16)) * 16384;

    LDSM_OFFSETS();
    float acc[2][8][4];
    #pragma unroll
    for (int i = 0; i < 2; i++)
        #pragma unroll
        for (int j = 0; j < 8; j++)
            #pragma unroll
            for (int k = 0; k < 4; k++) acc[i][j][k] = 0.f;

    GEMM_PIPELINE(16, Asrc, Bsrc);

    // epilogue: bias + SwiGLU -> swizzled smem tile -> contiguous 16KB store
    char* hsb = smem;
    #pragma unroll
    for (int mt = 0; mt < 2; mt++) {
        #pragma unroll
        for (int dd = 0; dd < 2; dd++) {
            int lrow = warp_m * 32 + mt * 16 + dd * 8 + (lane >> 2);
            #pragma unroll
            for (int nt = 0; nt < 8; nt++) {
                int colp = bx * BN + warp_n * 64 + nt * 8 + (lane & 3) * 2;
                float g = acc[mt][nt][dd * 2]     + b1[e * F2 + colp];
                float v = acc[mt][nt][dd * 2 + 1] + b1[e * F2 + colp + 1];
                g = fminf(g, 9.0f);
                v = fmaxf(fminf(v, 9.0f), -9.0f);
                float sig = 1.0f / (1.0f + __expf(-1.702f * g));
                float h = g * sig * (v + 1.0f);
                int hcol = warp_n * 32 + nt * 4 + (lane & 3);
                *(__half*)(hsb + lrow * 128 + ((hcol * 2) ^ ((lrow & 7) << 4))) =
                    __float2half_rn(h);
            }
        }
    }
    __syncthreads();
    uint4* dst = (uint4*)((char*)g_A2 + ((size_t)((e * 32 + blockIdx.y) * 32 + bx)) * 16384);
    const uint4* s4 = (const uint4*)hsb;
    #pragma unroll
    for (int j = 0; j < 4; j++)
        dst[tid + 256 * j] = s4[tid + 256 * j];
}

// ---------------- kernel 5: GEMM2 (y = H @ W2^T + b2) ----------------
__global__ void __launch_bounds__(256, 2) ffn2_mma(const float* __restrict__ b2) {
    extern __shared__ char smem[];
    __shared__ __align__(8) uint64_t mbars[NSTAGE];
    const int e = blockIdx.z;
    const int cnt = g_cnt[e];
    const int row0 = blockIdx.y * BM;
    if (row0 >= cnt) return;
    const int bx = blockIdx.x;

    const int tid = threadIdx.x;
    const int lane = tid & 31;
    const int warp_m = (tid >> 5) & 3;
    const int warp_n = tid >> 7;
    const uint32_t sb = smem_u32(smem), mb = smem_u32(mbars);

    const char* Asrc = (const char*)g_A2 + ((size_t)((e * 32 + blockIdx.y) * 32)) * 16384;
    const char* Bsrc = (const char*)g_B2 + ((size_t)((e * 8 + bx) * 32)) * 16384;

    LDSM_OFFSETS();
    float acc[2][8][4];
    #pragma unroll
    for (int i = 0; i < 2; i++)
        #pragma unroll
        for (int j = 0; j < 8; j++)
            #pragma unroll
            for (int k = 0; k < 4; k++) acc[i][j][k] = 0.f;

    GEMM_PIPELINE(32, Asrc, Bsrc);

    // epilogue: bias + fp32 y
    #pragma unroll
    for (int mt = 0; mt < 2; mt++) {
        #pragma unroll
        for (int dd = 0; dd < 2; dd++) {
            int lrow = warp_m * 32 + mt * 16 + dd * 8 + (lane >> 2);
            if (row0 + lrow >= cnt) continue;
            float* yrow = g_y + ((size_t)e * CAP + row0 + lrow) * D_DIM;
            #pragma unroll
            for (int nt = 0; nt < 8; nt++) {
                int col = bx * BN + warp_n * 64 + nt * 8 + (lane & 3) * 2;
                float2 o;
                o.x = acc[mt][nt][dd * 2]     + b2[e * D_DIM + col];
                o.y = acc[mt][nt][dd * 2 + 1] + b2[e * D_DIM + col + 1];
                *(float2*)(yrow + col) = o;
            }
        }
    }
}

// ---------------- kernel 6: deterministic weighted combine (float4) ----------------
__global__ void combine_kernel(float* __restrict__ out) {
    int t = blockIdx.x;
    int   e0 = g_t2e[t * 2 + 0], e1 = g_t2e[t * 2 + 1];
    float w0 = g_t2w[t * 2 + 0], w1 = g_t2w[t * 2 + 1];
    const float4* y0 = (const float4*)(g_y + (size_t)e0 * D_DIM);
    const float4* y1 = (const float4*)(g_y + (size_t)e1 * D_DIM);
    float4* o = (float4*)(out + (size_t)t * D_DIM);
    int i = threadIdx.x;                 // 256 threads x 1 float4 = 1024 floats
    float4 a = y0[i], b = y1[i];
    float4 r;
    r.x = w0 * a.x + w1 * b.x;
    r.y = w0 * a.y + w1 * b.y;
    r.z = w0 * a.z + w1 * b.z;
    r.w = w0 * a.w + w1 * b.w;
    o[i] = r;
}

extern "C" void kernel_launch(void* const* d_in, const int* in_sizes, int n_in,
                              void* d_out, int out_size) {
    const float* x  = (const float*)d_in[0];
    const float* gw = (const float*)d_in[1];
    const float* w1 = (const float*)d_in[2];
    const float* b1 = (const float*)d_in[3];
    const float* w2 = (const float*)d_in[4];
    const float* b2 = (const float*)d_in[5];
    float* out = (float*)d_out;

    static cudaStream_t s_cvt = nullptr;
    static cudaEvent_t ev_fork = nullptr, ev_join = nullptr;
    if (!s_cvt) {   // first call is the (non-captured) correctness run
        cudaStreamCreateWithFlags(&s_cvt, cudaStreamNonBlocking);
        cudaEventCreateWithFlags(&ev_fork, cudaEventDisableTiming);
        cudaEventCreateWithFlags(&ev_join, cudaEventDisableTiming);
        cudaFuncSetAttribute(ffn1_mma, cudaFuncAttributeMaxDynamicSharedMemorySize, SMEM_BYTES);
        cudaFuncSetAttribute(ffn2_mma, cudaFuncAttributeMaxDynamicSharedMemorySize, SMEM_BYTES);
    }

    zero_cnt_kernel<<<1, 32>>>();

    // fork: weight conversions run concurrently with gating+gather
    cudaEventRecord(ev_fork, 0);
    cudaStreamWaitEvent(s_cvt, ev_fork, 0);
    cvtW1_kernel<<<8192, 256, 0, s_cvt>>>(w1);
    cvtW2_kernel<<<4096, 256, 0, s_cvt>>>(w2);

    gate_kernel<<<T_TOK, 256>>>(x, gw);

    // join
    cudaEventRecord(ev_join, s_cvt);
    cudaStreamWaitEvent(0, ev_join, 0);

    ffn1_mma<<<dim3(F2 / BN, CAP / BM, E_NUM), 256, SMEM_BYTES>>>(b1);
    ffn2_mma<<<dim3(D_DIM / BN, CAP / BM, E_NUM), 256, SMEM_BYTES>>>(b2);
    combine_kernel<<<T_TOK, 256>>>(out);
}

// round 16
// speedup vs baseline: 1.3781x; 1.0757x over previous
#include <cuda_runtime.h>
#include <cuda_fp16.h>
#include <math.h>
#include <stdint.h>

// Problem constants
#define T_TOK 4096
#define D_DIM 1024
#define E_NUM 8
#define F_DIM 2048
#define F2    4096
#define CAP   4096

// Tile config: CTA 128x128x64, 8 warps (4m x 2n), warp tile 32x64
#define BM 128
#define BN 128
#define BK 64
#define MAT   16384                   // one operand tile: 128 rows x 128B (pre-swizzled)
#define STAGE (2 * MAT)               // A + B = 32768
#define NSTAGE 3
#define SMEM_BYTES (NSTAGE * STAGE)   // 98304 -> 2 CTAs/SM

// ---------------- scratch (device globals; no allocs allowed) ----------------
__device__ int   g_cnt[E_NUM];
__device__ int   g_t2e[T_TOK * 2];
__device__ float g_t2w[T_TOK * 2];
__device__ float g_gwT[E_NUM * D_DIM];   // transposed gate weights [E][D]
// tiled, SW128-pre-swizzled fp16 operand buffers (16KB tiles, kc innermost)
__device__ __align__(16) __half g_A1[(size_t)E_NUM * 32 * 16 * 8192];  // x gathered  [e][mt][kc]
__device__ __align__(16) __half g_B1[(size_t)E_NUM * 32 * 16 * 8192];  // w1          [e][nt][kc]
__device__ __align__(16) __half g_A2[(size_t)E_NUM * 32 * 32 * 8192];  // H           [e][mt][kc]
__device__ __align__(16) __half g_B2[(size_t)E_NUM * 8  * 32 * 8192];  // w2          [e][dt][kc]
__device__ float g_y[(size_t)E_NUM * CAP * D_DIM];

// ---------------- helpers ----------------
__device__ __forceinline__ uint32_t smem_u32(const void* p) {
    uint32_t a;
    asm("{ .reg .u64 t; cvta.to.shared.u64 t, %1; cvt.u32.u64 %0, t; }" : "=r"(a) : "l"(p));
    return a;
}
__device__ __forceinline__ void ldsm_x4(uint32_t& r0, uint32_t& r1, uint32_t& r2, uint32_t& r3,
                                        uint32_t addr) {
    asm volatile("ldmatrix.sync.aligned.m8n8.x4.shared.b16 {%0,%1,%2,%3}, [%4];"
                 : "=r"(r0), "=r"(r1), "=r"(r2), "=r"(r3) : "r"(addr));
}
__device__ __forceinline__ void mma_f16(float* c,
                                        uint32_t a0, uint32_t a1, uint32_t a2, uint32_t a3,
                                        uint32_t b0, uint32_t b1) {
    asm volatile("mma.sync.aligned.m16n8k16.row.col.f32.f16.f16.f32 "
                 "{%0,%1,%2,%3}, {%4,%5,%6,%7}, {%8,%9}, {%0,%1,%2,%3};"
                 : "+f"(c[0]), "+f"(c[1]), "+f"(c[2]), "+f"(c[3])
                 : "r"(a0), "r"(a1), "r"(a2), "r"(a3), "r"(b0), "r"(b1));
}
#define MBAR_INIT(a, c) \
    asm volatile("mbarrier.init.shared.b64 [%0], %1;" :: "r"(a), "r"(c) : "memory")
#define MBAR_EXPECT(a, tx) \
    asm volatile("mbarrier.arrive.expect_tx.shared.b64 _, [%0], %1;" :: "r"(a), "r"(tx) : "memory")
#define BULK16K(dst, src, mbar) \
    asm volatile("cp.async.bulk.shared::cluster.global.mbarrier::complete_tx::bytes [%0], [%1], 16384, [%2];" \
                 :: "r"(dst), "l"(src), "r"(mbar) : "memory")
#define MBAR_WAIT(addr, par) do { \
    uint32_t _m = (addr), _p = (par), _d; \
    asm volatile("{ .reg .pred p; mbarrier.try_wait.parity.acquire.cta.shared::cta.b64 p, [%1], %2; selp.b32 %0, 1, 0, p; }" \
        : "=r"(_d) : "r"(_m), "r"(_p) : "memory"); \
    if (!_d) { \
        asm volatile("{ .reg .pred P1; WL_%=: mbarrier.try_wait.parity.acquire.cta.shared::cta.b64 P1, [%0], %1, 0x989680; @P1 bra.uni WD_%=; bra.uni WL_%=; WD_%=: }" \
            :: "r"(_m), "r"(_p) : "memory"); \
    } } while (0)

// pack 8 fp32 -> 8 fp16 (16B)
__device__ __forceinline__ uint4 pack8(float4 a, float4 b) {
    __half2 h0 = __floats2half2_rn(a.x, a.y);
    __half2 h1 = __floats2half2_rn(a.z, a.w);
    __half2 h2 = __floats2half2_rn(b.x, b.y);
    __half2 h3 = __floats2half2_rn(b.z, b.w);
    uint4 r;
    r.x = *(uint32_t*)&h0; r.y = *(uint32_t*)&h1;
    r.z = *(uint32_t*)&h2; r.w = *(uint32_t*)&h3;
    return r;
}

// ---------------- kernel 0: reset counters + transpose gate weights ----------------
__global__ void init_kernel(const float* __restrict__ gw) {
    int i = blockIdx.x * blockDim.x + threadIdx.x;
    if (i < E_NUM) g_cnt[i] = 0;
    for (int j = i; j < E_NUM * D_DIM; j += gridDim.x * blockDim.x) {
        int e = j >> 10, d = j & 1023;
        g_gwT[j] = gw[d * E_NUM + e];
    }
}

// ---------------- kernel 1: gating + top-2 routing + FUSED x gather ----------------
__global__ void gate_kernel(const float* __restrict__ x) {
    int t = blockIdx.x;
    __shared__ float xs[D_DIM];
    __shared__ float gates[E_NUM];
    __shared__ int   sel_e[2], sel_slot[2];
    int tid = threadIdx.x;
    for (int i = tid; i < D_DIM; i += blockDim.x)
        xs[i] = x[(size_t)t * D_DIM + i];
    __syncthreads();
    int wid = tid >> 5, lane = tid & 31;
    // warp w computes expert w; g_gwT row read is lane-consecutive (no replay)
    const float* gwr = g_gwT + wid * D_DIM;
    float s = 0.f;
    for (int d = lane; d < D_DIM; d += 32)
        s += xs[d] * gwr[d];
    #pragma unroll
    for (int o = 16; o > 0; o >>= 1)
        s += __shfl_down_sync(0xffffffffu, s, o);
    if (lane == 0) gates[wid] = s;
    __syncthreads();
    if (tid == 0) {
        int i0 = 0; float g0 = gates[0];
        #pragma unroll
        for (int e = 1; e < E_NUM; e++)
            if (gates[e] > g0) { g0 = gates[e]; i0 = e; }
        int i1 = -1; float g1 = -1e30f;
        #pragma unroll
        for (int e = 0; e < E_NUM; e++)
            if (e != i0 && gates[e] > g1) { g1 = gates[e]; i1 = e; }
        float ex = expf(g1 - g0);
        float w0 = 1.f / (1.f + ex);
        float w1 = ex / (1.f + ex);
        int s0 = atomicAdd(&g_cnt[i0], 1);
        int s1 = atomicAdd(&g_cnt[i1], 1);
        sel_e[0] = i0; sel_slot[0] = s0;
        sel_e[1] = i1; sel_slot[1] = s1;
        g_t2e[t * 2 + 0] = i0 * CAP + s0;
        g_t2e[t * 2 + 1] = i1 * CAP + s1;
        g_t2w[t * 2 + 0] = w0;
        g_t2w[t * 2 + 1] = w1;
    }
    __syncthreads();
    // write this token's fp16 row into both experts' tiled A1 buffers
    int k = tid >> 7;            // entry 0 or 1
    int tt = tid & 127;          // 16B chunk within the row
    int e = sel_e[k], slot = sel_slot[k];
    float4 a = *(const float4*)(xs + tt * 8);
    float4 b = *(const float4*)(xs + tt * 8 + 4);
    uint4 v = pack8(a, b);
    int kc = tt >> 3, ch = tt & 7;
    size_t dstB = ((size_t)((e * 32 + (slot >> 7)) * 16 + kc)) * 16384
                + (slot & 127) * 128 + ((ch * 16) ^ ((slot & 7) << 4));
    *(uint4*)((char*)g_A1 + dstB) = v;
}

// ---------------- kernel 2: w1 fp32 -> tiled swizzled fp16 g_B1 ----------------
__global__ void cvtW1_kernel(const float* __restrict__ w1) {
    const int NCH = E_NUM * F2 * (D_DIM / 8);
    int i = blockIdx.x * blockDim.x + threadIdx.x;
    int stride = gridDim.x * blockDim.x;
    for (; i < NCH; i += stride) {
        int row = i >> 7, t = i & 127;
        const float4* src = (const float4*)(w1 + (size_t)row * D_DIM + t * 8);
        uint4 v = pack8(src[0], src[1]);
        int e = row >> 12, n = row & 4095;
        int nt = n >> 7, nr = n & 127;
        int kc = t >> 3, ch = t & 7;
        size_t dstB = ((size_t)((e * 32 + nt) * 16 + kc)) * 16384
                    + nr * 128 + ((ch * 16) ^ ((nr & 7) << 4));
        *(uint4*)((char*)g_B1 + dstB) = v;
    }
}

// ---------------- kernel 3: w2 fp32 -> tiled swizzled fp16 g_B2 ----------------
__global__ void cvtW2_kernel(const float* __restrict__ w2) {
    const int NCH = E_NUM * D_DIM * (F_DIM / 8);
    int i = blockIdx.x * blockDim.x + threadIdx.x;
    int stride = gridDim.x * blockDim.x;
    for (; i < NCH; i += stride) {
        int row = i >> 8, t = i & 255;
        const float4* src = (const float4*)(w2 + (size_t)row * F_DIM + t * 8);
        uint4 v = pack8(src[0], src[1]);
        int e = row >> 10, d = row & 1023;
        int dt = d >> 7, dr = d & 127;
        int kc = t >> 3, ch = t & 7;
        size_t dstB = ((size_t)((e * 8 + dt) * 32 + kc)) * 16384
                    + dr * 128 + ((ch * 16) ^ ((dr & 7) << 4));
        *(uint4*)((char*)g_B2 + dstB) = v;
    }
}

// ======================================================================
// GEMMs: bulk-copy mbarrier pipeline (unchanged).
// ======================================================================

#define LDSM_OFFSETS() \
    const int lj = lane >> 3, lr = lane & 7; \
    int a_row[2], a_sw[2], b_row[4], b_sw[4]; \
    const int a_chb = (lj >> 1) * 16; \
    const int b_chb = (lj & 1) * 16; \
    _Pragma("unroll") \
    for (int mt = 0; mt < 2; mt++) { \
        int ra = warp_m * 32 + mt * 16 + (lj & 1) * 8 + lr; \
        a_row[mt] = ra * 128; a_sw[mt] = (ra & 7) << 4; \
    } \
    _Pragma("unroll") \
    for (int np = 0; np < 4; np++) { \
        int rb = warp_n * 64 + np * 16 + (lj >> 1) * 8 + lr; \
        b_row[np] = rb * 128; b_sw[np] = (rb & 7) << 4; \
    }

#define MMA_COMPUTE(base) do { \
    _Pragma("unroll") \
    for (int kk = 0; kk < 4; kk++) { \
        uint32_t af[2][4]; \
        _Pragma("unroll") \
        for (int mt = 0; mt < 2; mt++) \
            ldsm_x4(af[mt][0], af[mt][1], af[mt][2], af[mt][3], \
                    (base) + a_row[mt] + ((kk * 32 + a_chb) ^ a_sw[mt])); \
        _Pragma("unroll") \
        for (int np = 0; np < 4; np++) { \
            uint32_t bf[4]; \
            ldsm_x4(bf[0], bf[1], bf[2], bf[3], \
                    (base) + MAT + b_row[np] + ((kk * 32 + b_chb) ^ b_sw[np])); \
            _Pragma("unroll") \
            for (int mt = 0; mt < 2; mt++) { \
                mma_f16(acc[mt][2 * np],     af[mt][0], af[mt][1], af[mt][2], af[mt][3], bf[0], bf[1]); \
                mma_f16(acc[mt][2 * np + 1], af[mt][0], af[mt][1], af[mt][2], af[mt][3], bf[2], bf[3]); \
            } \
        } \
    } } while (0)

#define GEMM_PIPELINE(NCHUNK, Asrc, Bsrc) do { \
    if (tid == 0) { \
        _Pragma("unroll") \
        for (int s = 0; s < NSTAGE; s++) MBAR_INIT(mb + 8 * s, 1); \
    } \
    __syncthreads(); \
    if (tid == 0) { \
        _Pragma("unroll") \
        for (int s = 0; s < NSTAGE; s++) { \
            MBAR_EXPECT(mb + 8 * s, 2 * MAT); \
            BULK16K(sb + s * STAGE,       (Asrc) + (size_t)s * MAT, mb + 8 * s); \
            BULK16K(sb + s * STAGE + MAT, (Bsrc) + (size_t)s * MAT, mb + 8 * s); \
        } \
    } \
    _Pragma("unroll 1") \
    for (int c = 0; c < (NCHUNK); c++) { \
        int s = c % 3; \
        MBAR_WAIT(mb + 8 * s, (c / 3) & 1); \
        MMA_COMPUTE(sb + s * STAGE); \
        __syncthreads(); \
        if (tid == 0 && c + 3 < (NCHUNK)) { \
            MBAR_EXPECT(mb + 8 * s, 2 * MAT); \
            BULK16K(sb + s * STAGE,       (Asrc) + (size_t)(c + 3) * MAT, mb + 8 * s); \
            BULK16K(sb + s * STAGE + MAT, (Bsrc) + (size_t)(c + 3) * MAT, mb + 8 * s); \
        } \
    } } while (0)

// ---------------- kernel 4: GEMM1 + SwiGLU -> tiled H (g_A2) ----------------
__global__ void __launch_bounds__(256, 2) ffn1_mma(const float* __restrict__ b1) {
    extern __shared__ char smem[];
    __shared__ __align__(8) uint64_t mbars[NSTAGE];
    const int e = blockIdx.z;
    const int cnt = g_cnt[e];
    const int row0 = blockIdx.y * BM;
    if (row0 >= cnt) return;
    const int bx = blockIdx.x;

    const int tid = threadIdx.x;
    const int lane = tid & 31;
    const int warp_m = (tid >> 5) & 3;
    const int warp_n = tid >> 7;
    const uint32_t sb = smem_u32(smem), mb = smem_u32(mbars);

    const char* Asrc = (const char*)g_A1 + ((size_t)((e * 32 + blockIdx.y) * 16)) * 16384;
    const char* Bsrc = (const char*)g_B1 + ((size_t)((e * 32 + bx) * 16)) * 16384;

    LDSM_OFFSETS();
    float acc[2][8][4];
    #pragma unroll
    for (int i = 0; i < 2; i++)
        #pragma unroll
        for (int j = 0; j < 8; j++)
            #pragma unroll
            for (int k = 0; k < 4; k++) acc[i][j][k] = 0.f;

    GEMM_PIPELINE(16, Asrc, Bsrc);

    // epilogue: bias + SwiGLU -> swizzled smem tile -> contiguous 16KB store
    char* hsb = smem;
    #pragma unroll
    for (int mt = 0; mt < 2; mt++) {
        #pragma unroll
        for (int dd = 0; dd < 2; dd++) {
            int lrow = warp_m * 32 + mt * 16 + dd * 8 + (lane >> 2);
            #pragma unroll
            for (int nt = 0; nt < 8; nt++) {
                int colp = bx * BN + warp_n * 64 + nt * 8 + (lane & 3) * 2;
                float g = acc[mt][nt][dd * 2]     + b1[e * F2 + colp];
                float v = acc[mt][nt][dd * 2 + 1] + b1[e * F2 + colp + 1];
                g = fminf(g, 9.0f);
                v = fmaxf(fminf(v, 9.0f), -9.0f);
                float sig = 1.0f / (1.0f + __expf(-1.702f * g));
                float h = g * sig * (v + 1.0f);
                int hcol = warp_n * 32 + nt * 4 + (lane & 3);
                *(__half*)(hsb + lrow * 128 + ((hcol * 2) ^ ((lrow & 7) << 4))) =
                    __float2half_rn(h);
            }
        }
    }
    __syncthreads();
    uint4* dst = (uint4*)((char*)g_A2 + ((size_t)((e * 32 + blockIdx.y) * 32 + bx)) * 16384);
    const uint4* s4 = (const uint4*)hsb;
    #pragma unroll
    for (int j = 0; j < 4; j++)
        dst[tid + 256 * j] = s4[tid + 256 * j];
}

// ---------------- kernel 5: GEMM2 (y = H @ W2^T + b2) ----------------
__global__ void __launch_bounds__(256, 2) ffn2_mma(const float* __restrict__ b2) {
    extern __shared__ char smem[];
    __shared__ __align__(8) uint64_t mbars[NSTAGE];
    const int e = blockIdx.z;
    const int cnt = g_cnt[e];
    const int row0 = blockIdx.y * BM;
    if (row0 >= cnt) return;
    const int bx = blockIdx.x;

    const int tid = threadIdx.x;
    const int lane = tid & 31;
    const int warp_m = (tid >> 5) & 3;
    const int warp_n = tid >> 7;
    const uint32_t sb = smem_u32(smem), mb = smem_u32(mbars);

    const char* Asrc = (const char*)g_A2 + ((size_t)((e * 32 + blockIdx.y) * 32)) * 16384;
    const char* Bsrc = (const char*)g_B2 + ((size_t)((e * 8 + bx) * 32)) * 16384;

    LDSM_OFFSETS();
    float acc[2][8][4];
    #pragma unroll
    for (int i = 0; i < 2; i++)
        #pragma unroll
        for (int j = 0; j < 8; j++)
            #pragma unroll
            for (int k = 0; k < 4; k++) acc[i][j][k] = 0.f;

    GEMM_PIPELINE(32, Asrc, Bsrc);

    // epilogue: bias + fp32 y
    #pragma unroll
    for (int mt = 0; mt < 2; mt++) {
        #pragma unroll
        for (int dd = 0; dd < 2; dd++) {
            int lrow = warp_m * 32 + mt * 16 + dd * 8 + (lane >> 2);
            if (row0 + lrow >= cnt) continue;
            float* yrow = g_y + ((size_t)e * CAP + row0 + lrow) * D_DIM;
            #pragma unroll
            for (int nt = 0; nt < 8; nt++) {
                int col = bx * BN + warp_n * 64 + nt * 8 + (lane & 3) * 2;
                float2 o;
                o.x = acc[mt][nt][dd * 2]     + b2[e * D_DIM + col];
                o.y = acc[mt][nt][dd * 2 + 1] + b2[e * D_DIM + col + 1];
                *(float2*)(yrow + col) = o;
            }
        }
    }
}

// ---------------- kernel 6: deterministic weighted combine (float4) ----------------
__global__ void combine_kernel(float* __restrict__ out) {
    int t = blockIdx.x;
    int   e0 = g_t2e[t * 2 + 0], e1 = g_t2e[t * 2 + 1];
    float w0 = g_t2w[t * 2 + 0], w1 = g_t2w[t * 2 + 1];
    const float4* y0 = (const float4*)(g_y + (size_t)e0 * D_DIM);
    const float4* y1 = (const float4*)(g_y + (size_t)e1 * D_DIM);
    float4* o = (float4*)(out + (size_t)t * D_DIM);
    int i = threadIdx.x;
    float4 a = y0[i], b = y1[i];
    float4 r;
    r.x = w0 * a.x + w1 * b.x;
    r.y = w0 * a.y + w1 * b.y;
    r.z = w0 * a.z + w1 * b.z;
    r.w = w0 * a.w + w1 * b.w;
    o[i] = r;
}

extern "C" void kernel_launch(void* const* d_in, const int* in_sizes, int n_in,
                              void* d_out, int out_size) {
    const float* x  = (const float*)d_in[0];
    const float* gw = (const float*)d_in[1];
    const float* w1 = (const float*)d_in[2];
    const float* b1 = (const float*)d_in[3];
    const float* w2 = (const float*)d_in[4];
    const float* b2 = (const float*)d_in[5];
    float* out = (float*)d_out;

    static cudaStream_t s_cvt = nullptr;
    static cudaEvent_t ev_fork = nullptr, ev_j1 = nullptr, ev_j2 = nullptr;
    if (!s_cvt) {   // first call is the (non-captured) correctness run
        cudaStreamCreateWithFlags(&s_cvt, cudaStreamNonBlocking);
        cudaEventCreateWithFlags(&ev_fork, cudaEventDisableTiming);
        cudaEventCreateWithFlags(&ev_j1, cudaEventDisableTiming);
        cudaEventCreateWithFlags(&ev_j2, cudaEventDisableTiming);
        cudaFuncSetAttribute(ffn1_mma, cudaFuncAttributeMaxDynamicSharedMemorySize, SMEM_BYTES);
        cudaFuncSetAttribute(ffn2_mma, cudaFuncAttributeMaxDynamicSharedMemorySize, SMEM_BYTES);
    }

    // fork: weight conversions run on side stream
    cudaEventRecord(ev_fork, 0);
    cudaStreamWaitEvent(s_cvt, ev_fork, 0);
    cvtW1_kernel<<<8192, 256, 0, s_cvt>>>(w1);
    cudaEventRecord(ev_j1, s_cvt);            // ffn1 needs only B1
    cvtW2_kernel<<<4096, 256, 0, s_cvt>>>(w2);
    cudaEventRecord(ev_j2, s_cvt);            // ffn2 needs B2

    // main stream: routing (+ fused x gather)
    init_kernel<<<32, 256>>>(gw);
    gate_kernel<<<T_TOK, 256>>>(x);

    cudaStreamWaitEvent(0, ev_j1, 0);
    ffn1_mma<<<dim3(F2 / BN, CAP / BM, E_NUM), 256, SMEM_BYTES>>>(b1);
    cudaStreamWaitEvent(0, ev_j2, 0);
    ffn2_mma<<<dim3(D_DIM / BN, CAP / BM, E_NUM), 256, SMEM_BYTES>>>(b2);
    combine_kernel<<<T_TOK, 256>>>(out);
}